// round 1
// baseline (speedup 1.0000x reference)
#include <cuda_runtime.h>
#include <math.h>

// ---- problem constants ----
#define D_   2048
#define H_   16
#define KVH_ 4
#define HD_  128
#define B_   2
#define T_   2048
#define BT_  (B_*T_)          // 4096
#define QCOLS_ (H_*HD_)       // 2048
#define KCOLS_ (KVH_*HD_)     // 512
#define CAP_ 50.0f
#define SCALE_ 0.08838834764831845f  // 128^-0.5

// ---- scratch (static device arrays; no allocations allowed) ----
static __device__ float g_q[BT_*QCOLS_];
static __device__ float g_k[BT_*KCOLS_];
static __device__ float g_v[BT_*KCOLS_];
static __device__ float g_o[BT_*QCOLS_];

// ============================================================================
// GEMM: C[M,N] = A[M,K] * B[N,K]^T   (both row-major). M,N mult of 128, K of 16.
// 128x128x16 tiles, 256 threads, 8x8 per thread, col/row mapping tx+16j / ty+16i.
// ============================================================================
__global__ __launch_bounds__(256) void gemm_abt(
    const float* __restrict__ A, const float* __restrict__ Bw,
    float* __restrict__ C, int M, int N, int K)
{
    __shared__ float As[128*17];
    __shared__ float Bs[128*17];
    const int tid = threadIdx.x;
    const int tx = tid & 15, ty = tid >> 4;
    const int rowBase = blockIdx.y * 128;
    const int colBase = blockIdx.x * 128;

    float acc[8][8];
#pragma unroll
    for (int i = 0; i < 8; i++)
#pragma unroll
        for (int j = 0; j < 8; j++) acc[i][j] = 0.f;

    for (int k0 = 0; k0 < K; k0 += 16) {
        // load 128x16 A and B tiles: 512 float4, 2 per thread each
#pragma unroll
        for (int it = 0; it < 2; it++) {
            int i  = it * 256 + tid;
            int r  = i >> 2;
            int c4 = (i & 3) << 2;
            float4 va = *(const float4*)(A  + (size_t)(rowBase + r) * K + k0 + c4);
            As[r*17 + c4+0] = va.x; As[r*17 + c4+1] = va.y;
            As[r*17 + c4+2] = va.z; As[r*17 + c4+3] = va.w;
            float4 vb = *(const float4*)(Bw + (size_t)(colBase + r) * K + k0 + c4);
            Bs[r*17 + c4+0] = vb.x; Bs[r*17 + c4+1] = vb.y;
            Bs[r*17 + c4+2] = vb.z; Bs[r*17 + c4+3] = vb.w;
        }
        __syncthreads();

#pragma unroll
        for (int kk = 0; kk < 16; kk++) {
            float a[8], b[8];
#pragma unroll
            for (int i = 0; i < 8; i++) a[i] = As[(ty + 16*i)*17 + kk];
#pragma unroll
            for (int j = 0; j < 8; j++) b[j] = Bs[(tx + 16*j)*17 + kk];
#pragma unroll
            for (int i = 0; i < 8; i++)
#pragma unroll
                for (int j = 0; j < 8; j++)
                    acc[i][j] = fmaf(a[i], b[j], acc[i][j]);
        }
        __syncthreads();
    }

#pragma unroll
    for (int i = 0; i < 8; i++) {
        int r = rowBase + ty + 16*i;
#pragma unroll
        for (int j = 0; j < 8; j++) {
            int c = colBase + tx + 16*j;
            C[(size_t)r * N + c] = acc[i][j];
        }
    }
}

// ============================================================================
// RMSNorm: one warp per 128-element row, in place. Scale folded in (q gets HD^-0.5).
// ============================================================================
__global__ __launch_bounds__(256) void rmsnorm_k(
    float* __restrict__ data, const float* __restrict__ gamma,
    int nrows, float scale)
{
    int row  = blockIdx.x * 8 + (threadIdx.x >> 5);
    int lane = threadIdx.x & 31;
    if (row >= nrows) return;
    float4 v = ((float4*)data)[(size_t)row * 32 + lane];
    float ss = v.x*v.x + v.y*v.y + v.z*v.z + v.w*v.w;
#pragma unroll
    for (int off = 16; off > 0; off >>= 1)
        ss += __shfl_xor_sync(0xffffffffu, ss, off);
    float r = rsqrtf(ss * (1.0f/128.0f) + 1e-6f) * scale;
    float4 g = ((const float4*)gamma)[lane];
    v.x *= r * g.x; v.y *= r * g.y; v.z *= r * g.z; v.w *= r * g.w;
    ((float4*)data)[(size_t)row * 32 + lane] = v;
}

// ============================================================================
// Flash attention (causal, tanh softcap). 64 q-rows x 64 k-cols per tile.
// 256 threads: thread (ty,tx) owns score rows 4ty+i, score cols tx+16j,
// and output rows 4ty+i, cols 8tx..8tx+7. Row groups = 16 contiguous lanes.
// smem: Qs/Ks/Vs [64][132] (pad-132, float4 clean), Pt [64][68] transposed P.
// ============================================================================
#define SM_ROWPAD 132
#define PT_PAD    68
#define ATTN_SMEM ((3*64*SM_ROWPAD + 64*PT_PAD) * (int)sizeof(float))

__global__ __launch_bounds__(256) void attn_k(
    const float* __restrict__ Q, const float* __restrict__ Kk,
    const float* __restrict__ Vv, float* __restrict__ O)
{
    extern __shared__ float sm[];
    float* Qs = sm;
    float* Ks = Qs + 64*SM_ROWPAD;
    float* Vs = Ks + 64*SM_ROWPAD;
    float* Pt = Vs + 64*SM_ROWPAD;

    const int tid = threadIdx.x;
    const int tx = tid & 15, ty = tid >> 4;
    const int bh = blockIdx.y;
    const int b = bh >> 4, h = bh & 15, kvh = h >> 2;
    const int qTile = gridDim.x - 1 - blockIdx.x;   // heavy tiles first
    const int qBase = qTile * 64;

    const float* qp = Q  + (size_t)b*T_*QCOLS_ + (size_t)h*HD_;
    const float* kp = Kk + (size_t)b*T_*KCOLS_ + (size_t)kvh*HD_;
    const float* vp = Vv + (size_t)b*T_*KCOLS_ + (size_t)kvh*HD_;

    // load Q tile (64 rows x 128) -> Qs
#pragma unroll
    for (int it = 0; it < 8; it++) {
        int i  = it * 256 + tid;
        int r  = i >> 5;
        int c4 = (i & 31) << 2;
        *(float4*)(Qs + r*SM_ROWPAD + c4) =
            *(const float4*)(qp + (size_t)(qBase + r) * QCOLS_ + c4);
    }

    float m[4], l[4], acc[4][8];
#pragma unroll
    for (int i = 0; i < 4; i++) {
        m[i] = -INFINITY; l[i] = 0.f;
#pragma unroll
        for (int c = 0; c < 8; c++) acc[i][c] = 0.f;
    }

    const int jmax = qBase >> 6;
    for (int jt = 0; jt <= jmax; jt++) {
        const int kBase = jt * 64;
        // load K and V tiles
#pragma unroll
        for (int it = 0; it < 8; it++) {
            int i  = it * 256 + tid;
            int r  = i >> 5;
            int c4 = (i & 31) << 2;
            *(float4*)(Ks + r*SM_ROWPAD + c4) =
                *(const float4*)(kp + (size_t)(kBase + r) * KCOLS_ + c4);
            *(float4*)(Vs + r*SM_ROWPAD + c4) =
                *(const float4*)(vp + (size_t)(kBase + r) * KCOLS_ + c4);
        }
        __syncthreads();

        // S = Q . K^T  (scale already folded into Q)
        float s[4][4];
#pragma unroll
        for (int i = 0; i < 4; i++)
#pragma unroll
            for (int j = 0; j < 4; j++) s[i][j] = 0.f;

        for (int d = 0; d < 128; d += 4) {
            float4 a[4], bb[4];
#pragma unroll
            for (int i = 0; i < 4; i++)
                a[i] = *(const float4*)(Qs + (4*ty + i)*SM_ROWPAD + d);
#pragma unroll
            for (int j = 0; j < 4; j++)
                bb[j] = *(const float4*)(Ks + (tx + 16*j)*SM_ROWPAD + d);
#pragma unroll
            for (int i = 0; i < 4; i++)
#pragma unroll
                for (int j = 0; j < 4; j++) {
                    s[i][j] = fmaf(a[i].x, bb[j].x, s[i][j]);
                    s[i][j] = fmaf(a[i].y, bb[j].y, s[i][j]);
                    s[i][j] = fmaf(a[i].z, bb[j].z, s[i][j]);
                    s[i][j] = fmaf(a[i].w, bb[j].w, s[i][j]);
                }
        }

        // softcap + causal mask
#pragma unroll
        for (int i = 0; i < 4; i++) {
            int qi = qBase + 4*ty + i;
#pragma unroll
            for (int j = 0; j < 4; j++) {
                int ki = kBase + tx + 16*j;
                float val = CAP_ * tanhf(s[i][j] * (1.0f/CAP_));
                s[i][j] = (ki > qi) ? -INFINITY : val;
            }
        }

        // online softmax (row = 16 contiguous lanes; shfl offsets 1..8 stay in group)
        float alpha[4], rsum[4];
#pragma unroll
        for (int i = 0; i < 4; i++) {
            float rmax = fmaxf(fmaxf(s[i][0], s[i][1]), fmaxf(s[i][2], s[i][3]));
#pragma unroll
            for (int off = 1; off <= 8; off <<= 1)
                rmax = fmaxf(rmax, __shfl_xor_sync(0xffffffffu, rmax, off));
            float mn = fmaxf(m[i], rmax);
            alpha[i] = __expf(m[i] - mn);
            m[i] = mn;
            float rs = 0.f;
#pragma unroll
            for (int j = 0; j < 4; j++) {
                float p = __expf(s[i][j] - mn);
                rs += p;
                s[i][j] = p;
            }
#pragma unroll
            for (int off = 1; off <= 8; off <<= 1)
                rs += __shfl_xor_sync(0xffffffffu, rs, off);
            rsum[i] = rs;
        }

        // write transposed P, update l and rescale acc
#pragma unroll
        for (int i = 0; i < 4; i++) {
#pragma unroll
            for (int j = 0; j < 4; j++)
                Pt[(tx + 16*j)*PT_PAD + 4*ty + i] = s[i][j];
            l[i] = l[i]*alpha[i] + rsum[i];
#pragma unroll
            for (int c = 0; c < 8; c++) acc[i][c] *= alpha[i];
        }
        __syncthreads();

        // O += P . V
        for (int s0 = 0; s0 < 64; s0++) {
            float4 a4 = *(const float4*)(Pt + s0*PT_PAD + 4*ty);
            float4 v0 = *(const float4*)(Vs + s0*SM_ROWPAD + 8*tx);
            float4 v1 = *(const float4*)(Vs + s0*SM_ROWPAD + 8*tx + 4);
            float aa[4] = {a4.x, a4.y, a4.z, a4.w};
#pragma unroll
            for (int i = 0; i < 4; i++) {
                acc[i][0] = fmaf(aa[i], v0.x, acc[i][0]);
                acc[i][1] = fmaf(aa[i], v0.y, acc[i][1]);
                acc[i][2] = fmaf(aa[i], v0.z, acc[i][2]);
                acc[i][3] = fmaf(aa[i], v0.w, acc[i][3]);
                acc[i][4] = fmaf(aa[i], v1.x, acc[i][4]);
                acc[i][5] = fmaf(aa[i], v1.y, acc[i][5]);
                acc[i][6] = fmaf(aa[i], v1.z, acc[i][6]);
                acc[i][7] = fmaf(aa[i], v1.w, acc[i][7]);
            }
        }
        __syncthreads();
    }

    // epilogue: divide by l, write to (b,t,h,hd) layout
    float* op = O + ((size_t)b*T_ + qBase) * QCOLS_ + (size_t)h*HD_;
#pragma unroll
    for (int i = 0; i < 4; i++) {
        float inv = 1.0f / l[i];
        float4 o0 = make_float4(acc[i][0]*inv, acc[i][1]*inv, acc[i][2]*inv, acc[i][3]*inv);
        float4 o1 = make_float4(acc[i][4]*inv, acc[i][5]*inv, acc[i][6]*inv, acc[i][7]*inv);
        *(float4*)(op + (size_t)(4*ty + i)*QCOLS_ + 8*tx)     = o0;
        *(float4*)(op + (size_t)(4*ty + i)*QCOLS_ + 8*tx + 4) = o1;
    }
}

// ============================================================================
// launch
// ============================================================================
extern "C" void kernel_launch(void* const* d_in, const int* in_sizes, int n_in,
                              void* d_out, int out_size)
{
    const float* x  = (const float*)d_in[0];
    const float* wq = (const float*)d_in[1];
    const float* wk = (const float*)d_in[2];
    const float* wv = (const float*)d_in[3];
    const float* wo = (const float*)d_in[4];
    const float* qg = (const float*)d_in[5];
    const float* kg = (const float*)d_in[6];
    float* out = (float*)d_out;

    float *q, *k, *v, *o;
    cudaGetSymbolAddress((void**)&q, g_q);
    cudaGetSymbolAddress((void**)&k, g_k);
    cudaGetSymbolAddress((void**)&v, g_v);
    cudaGetSymbolAddress((void**)&o, g_o);

    // projections
    gemm_abt<<<dim3(QCOLS_/128, BT_/128), 256>>>(x, wq, q, BT_, QCOLS_, D_);
    gemm_abt<<<dim3(KCOLS_/128, BT_/128), 256>>>(x, wk, k, BT_, KCOLS_, D_);
    gemm_abt<<<dim3(KCOLS_/128, BT_/128), 256>>>(x, wv, v, BT_, KCOLS_, D_);

    // QK-norm (fold attention scale into q)
    rmsnorm_k<<<(BT_*H_)/8, 256>>>(q, qg, BT_*H_, SCALE_);
    rmsnorm_k<<<(BT_*KVH_)/8, 256>>>(k, kg, BT_*KVH_, 1.0f);

    // attention
    cudaFuncSetAttribute(attn_k, cudaFuncAttributeMaxDynamicSharedMemorySize, ATTN_SMEM);
    attn_k<<<dim3(T_/64, B_*H_), 256, ATTN_SMEM>>>(q, k, v, o);

    // output projection
    gemm_abt<<<dim3(D_/128, BT_/128), 256>>>(o, wo, out, BT_, D_, D_);
}

// round 4
// speedup vs baseline: 1.8937x; 1.8937x over previous
#include <cuda_runtime.h>
#include <math.h>

// ---- problem constants ----
#define D_   2048
#define H_   16
#define KVH_ 4
#define HD_  128
#define B_   2
#define T_   2048
#define BT_  (B_*T_)          // 4096
#define QCOLS_ (H_*HD_)       // 2048
#define KCOLS_ (KVH_*HD_)     // 512
#define CAP_ 50.0f
#define SCALE_ 0.08838834764831845f  // 128^-0.5

// ---- scratch (static device arrays; no allocations allowed) ----
static __device__ float g_q[BT_*QCOLS_];
static __device__ float g_k[BT_*KCOLS_];
static __device__ float g_v[BT_*KCOLS_];
static __device__ float g_o[BT_*QCOLS_];

// ============================================================================
// tf32 mma helpers
// ============================================================================
__device__ __forceinline__ unsigned f2tf32(float x) {
    unsigned u;
    asm("cvt.rna.tf32.f32 %0, %1;" : "=r"(u) : "f"(x));
    return u;
}

__device__ __forceinline__ void mma_tf32(float* c, const unsigned* a, const unsigned* b) {
    asm volatile(
        "mma.sync.aligned.m16n8k8.row.col.f32.tf32.tf32.f32 "
        "{%0,%1,%2,%3}, {%4,%5,%6,%7}, {%8,%9}, {%0,%1,%2,%3};"
        : "+f"(c[0]), "+f"(c[1]), "+f"(c[2]), "+f"(c[3])
        : "r"(a[0]), "r"(a[1]), "r"(a[2]), "r"(a[3]), "r"(b[0]), "r"(b[1]));
}

__device__ __forceinline__ void cp_async16(void* smem_dst, const void* gsrc) {
    unsigned saddr = (unsigned)__cvta_generic_to_shared(smem_dst);
    asm volatile("cp.async.cg.shared.global [%0], [%1], 16;" :: "r"(saddr), "l"(gsrc));
}
#define CP_COMMIT() asm volatile("cp.async.commit_group;")
#define CP_WAIT0()  asm volatile("cp.async.wait_group 0;")

// ============================================================================
// tf32 tensor-core GEMM: C[M,N] = A[M,K] * B[N,K]^T  (row-major, M,N %128==0,
// K %32==0). 128x128x32 CTA tile, 8 warps (4x2), warp tile 32x64,
// 2-stage cp.async pipeline. smem rows padded to 36 floats (conflict-free).
// ============================================================================
#define BK_ 32
#define LDP_ 36
#define GEMM_SMEM (4 * 128 * LDP_ * (int)sizeof(float))  // 2 stages x (A+B)

__global__ __launch_bounds__(256) void gemm_tf32(
    const float* __restrict__ A, const float* __restrict__ Bw,
    float* __restrict__ C, int M, int N, int K)
{
    extern __shared__ float sm[];
    float* AsBase = sm;                    // [2][128*LDP_]
    float* BsBase = sm + 2 * 128 * LDP_;   // [2][128*LDP_]

    const int tid  = threadIdx.x;
    const int lane = tid & 31;
    const int warp = tid >> 5;
    const int wm = (warp & 3) * 32;    // warp row offset within tile
    const int wn = (warp >> 2) * 64;   // warp col offset within tile
    const int rowBase = blockIdx.y * 128;
    const int colBase = blockIdx.x * 128;

    const int lr = tid >> 3;          // load row sub-index (0..31)
    const int lc = (tid & 7) * 4;     // load col (float index, 16B steps)

    float acc[2][8][4];
#pragma unroll
    for (int mi = 0; mi < 2; mi++)
#pragma unroll
        for (int ni = 0; ni < 8; ni++)
#pragma unroll
            for (int q = 0; q < 4; q++) acc[mi][ni][q] = 0.f;

    const int ntiles = K / BK_;

    // ---- prologue: stage 0 ----
    {
        float* as = AsBase;
        float* bs = BsBase;
#pragma unroll
        for (int it = 0; it < 4; it++) {
            int r = it * 32 + lr;
            cp_async16(as + r * LDP_ + lc, A  + (size_t)(rowBase + r) * K + lc);
            cp_async16(bs + r * LDP_ + lc, Bw + (size_t)(colBase + r) * K + lc);
        }
        CP_COMMIT();
    }

    int cur = 0;
    for (int t = 0; t < ntiles; t++) {
        CP_WAIT0();
        __syncthreads();

        if (t + 1 < ntiles) {
            int k0 = (t + 1) * BK_;
            float* as = AsBase + (cur ^ 1) * 128 * LDP_;
            float* bs = BsBase + (cur ^ 1) * 128 * LDP_;
#pragma unroll
            for (int it = 0; it < 4; it++) {
                int r = it * 32 + lr;
                cp_async16(as + r * LDP_ + lc, A  + (size_t)(rowBase + r) * K + k0 + lc);
                cp_async16(bs + r * LDP_ + lc, Bw + (size_t)(colBase + r) * K + k0 + lc);
            }
            CP_COMMIT();
        }

        const float* as = AsBase + cur * 128 * LDP_;
        const float* bs = BsBase + cur * 128 * LDP_;
#pragma unroll
        for (int kk = 0; kk < 4; kk++) {
            const int k = kk * 8 + (lane & 3);
            unsigned af[2][4], bf[8][2];
#pragma unroll
            for (int mi = 0; mi < 2; mi++) {
                int r = wm + mi * 16 + (lane >> 2);
                af[mi][0] = f2tf32(as[r       * LDP_ + k]);
                af[mi][1] = f2tf32(as[(r + 8) * LDP_ + k]);
                af[mi][2] = f2tf32(as[r       * LDP_ + k + 4]);
                af[mi][3] = f2tf32(as[(r + 8) * LDP_ + k + 4]);
            }
#pragma unroll
            for (int ni = 0; ni < 8; ni++) {
                int n = wn + ni * 8 + (lane >> 2);
                bf[ni][0] = f2tf32(bs[n * LDP_ + k]);
                bf[ni][1] = f2tf32(bs[n * LDP_ + k + 4]);
            }
#pragma unroll
            for (int mi = 0; mi < 2; mi++)
#pragma unroll
                for (int ni = 0; ni < 8; ni++)
                    mma_tf32(acc[mi][ni], af[mi], bf[ni]);
        }
        cur ^= 1;
    }

    // ---- epilogue ----
#pragma unroll
    for (int mi = 0; mi < 2; mi++) {
        int r0 = rowBase + wm + mi * 16 + (lane >> 2);
#pragma unroll
        for (int ni = 0; ni < 8; ni++) {
            int c0 = colBase + wn + ni * 8 + (lane & 3) * 2;
            *(float2*)&C[(size_t)r0       * N + c0] = make_float2(acc[mi][ni][0], acc[mi][ni][1]);
            *(float2*)&C[(size_t)(r0 + 8) * N + c0] = make_float2(acc[mi][ni][2], acc[mi][ni][3]);
        }
    }
}

// ============================================================================
// RMSNorm: one warp per 128-element row, in place. Scale folded in (q gets HD^-0.5).
// ============================================================================
__global__ __launch_bounds__(256) void rmsnorm_k(
    float* __restrict__ data, const float* __restrict__ gamma,
    int nrows, float scale)
{
    int row  = blockIdx.x * 8 + (threadIdx.x >> 5);
    int lane = threadIdx.x & 31;
    if (row >= nrows) return;
    float4 v = ((float4*)data)[(size_t)row * 32 + lane];
    float ss = v.x*v.x + v.y*v.y + v.z*v.z + v.w*v.w;
#pragma unroll
    for (int off = 16; off > 0; off >>= 1)
        ss += __shfl_xor_sync(0xffffffffu, ss, off);
    float r = rsqrtf(ss * (1.0f/128.0f) + 1e-6f) * scale;
    float4 g = ((const float4*)gamma)[lane];
    v.x *= r * g.x; v.y *= r * g.y; v.z *= r * g.z; v.w *= r * g.w;
    ((float4*)data)[(size_t)row * 32 + lane] = v;
}

// ============================================================================
// Flash attention (causal, tanh softcap). 64 q-rows x 64 k-cols per tile.
// 256 threads: thread (ty,tx) owns score rows 4ty+i, score cols tx+16j,
// and output rows 4ty+i, cols 8tx..8tx+7. Row groups = 16 contiguous lanes.
// smem: Qs/Ks/Vs [64][132] (pad-132, float4 clean), Pt [64][68] transposed P.
// ============================================================================
#define SM_ROWPAD 132
#define PT_PAD    68
#define ATTN_SMEM ((3*64*SM_ROWPAD + 64*PT_PAD) * (int)sizeof(float))

__global__ __launch_bounds__(256) void attn_k(
    const float* __restrict__ Q, const float* __restrict__ Kk,
    const float* __restrict__ Vv, float* __restrict__ O)
{
    extern __shared__ float sm[];
    float* Qs = sm;
    float* Ks = Qs + 64*SM_ROWPAD;
    float* Vs = Ks + 64*SM_ROWPAD;
    float* Pt = Vs + 64*SM_ROWPAD;

    const int tid = threadIdx.x;
    const int tx = tid & 15, ty = tid >> 4;
    const int bh = blockIdx.y;
    const int b = bh >> 4, h = bh & 15, kvh = h >> 2;
    const int qTile = gridDim.x - 1 - blockIdx.x;   // heavy tiles first
    const int qBase = qTile * 64;

    const float* qp = Q  + (size_t)b*T_*QCOLS_ + (size_t)h*HD_;
    const float* kp = Kk + (size_t)b*T_*KCOLS_ + (size_t)kvh*HD_;
    const float* vp = Vv + (size_t)b*T_*KCOLS_ + (size_t)kvh*HD_;

    // load Q tile (64 rows x 128) -> Qs
#pragma unroll
    for (int it = 0; it < 8; it++) {
        int i  = it * 256 + tid;
        int r  = i >> 5;
        int c4 = (i & 31) << 2;
        *(float4*)(Qs + r*SM_ROWPAD + c4) =
            *(const float4*)(qp + (size_t)(qBase + r) * QCOLS_ + c4);
    }

    float m[4], l[4], acc[4][8];
#pragma unroll
    for (int i = 0; i < 4; i++) {
        m[i] = -INFINITY; l[i] = 0.f;
#pragma unroll
        for (int c = 0; c < 8; c++) acc[i][c] = 0.f;
    }

    const int jmax = qBase >> 6;
    for (int jt = 0; jt <= jmax; jt++) {
        const int kBase = jt * 64;
#pragma unroll
        for (int it = 0; it < 8; it++) {
            int i  = it * 256 + tid;
            int r  = i >> 5;
            int c4 = (i & 31) << 2;
            *(float4*)(Ks + r*SM_ROWPAD + c4) =
                *(const float4*)(kp + (size_t)(kBase + r) * KCOLS_ + c4);
            *(float4*)(Vs + r*SM_ROWPAD + c4) =
                *(const float4*)(vp + (size_t)(kBase + r) * KCOLS_ + c4);
        }
        __syncthreads();

        float s[4][4];
#pragma unroll
        for (int i = 0; i < 4; i++)
#pragma unroll
            for (int j = 0; j < 4; j++) s[i][j] = 0.f;

        for (int d = 0; d < 128; d += 4) {
            float4 a[4], bb[4];
#pragma unroll
            for (int i = 0; i < 4; i++)
                a[i] = *(const float4*)(Qs + (4*ty + i)*SM_ROWPAD + d);
#pragma unroll
            for (int j = 0; j < 4; j++)
                bb[j] = *(const float4*)(Ks + (tx + 16*j)*SM_ROWPAD + d);
#pragma unroll
            for (int i = 0; i < 4; i++)
#pragma unroll
                for (int j = 0; j < 4; j++) {
                    s[i][j] = fmaf(a[i].x, bb[j].x, s[i][j]);
                    s[i][j] = fmaf(a[i].y, bb[j].y, s[i][j]);
                    s[i][j] = fmaf(a[i].z, bb[j].z, s[i][j]);
                    s[i][j] = fmaf(a[i].w, bb[j].w, s[i][j]);
                }
        }

#pragma unroll
        for (int i = 0; i < 4; i++) {
            int qi = qBase + 4*ty + i;
#pragma unroll
            for (int j = 0; j < 4; j++) {
                int ki = kBase + tx + 16*j;
                float val = CAP_ * tanhf(s[i][j] * (1.0f/CAP_));
                s[i][j] = (ki > qi) ? -INFINITY : val;
            }
        }

        float alpha[4], rsum[4];
#pragma unroll
        for (int i = 0; i < 4; i++) {
            float rmax = fmaxf(fmaxf(s[i][0], s[i][1]), fmaxf(s[i][2], s[i][3]));
#pragma unroll
            for (int off = 1; off <= 8; off <<= 1)
                rmax = fmaxf(rmax, __shfl_xor_sync(0xffffffffu, rmax, off));
            float mn = fmaxf(m[i], rmax);
            alpha[i] = __expf(m[i] - mn);
            m[i] = mn;
            float rs = 0.f;
#pragma unroll
            for (int j = 0; j < 4; j++) {
                float p = __expf(s[i][j] - mn);
                rs += p;
                s[i][j] = p;
            }
#pragma unroll
            for (int off = 1; off <= 8; off <<= 1)
                rs += __shfl_xor_sync(0xffffffffu, rs, off);
            rsum[i] = rs;
        }

#pragma unroll
        for (int i = 0; i < 4; i++) {
#pragma unroll
            for (int j = 0; j < 4; j++)
                Pt[(tx + 16*j)*PT_PAD + 4*ty + i] = s[i][j];
            l[i] = l[i]*alpha[i] + rsum[i];
#pragma unroll
            for (int c = 0; c < 8; c++) acc[i][c] *= alpha[i];
        }
        __syncthreads();

        for (int s0 = 0; s0 < 64; s0++) {
            float4 a4 = *(const float4*)(Pt + s0*PT_PAD + 4*ty);
            float4 v0 = *(const float4*)(Vs + s0*SM_ROWPAD + 8*tx);
            float4 v1 = *(const float4*)(Vs + s0*SM_ROWPAD + 8*tx + 4);
            float aa[4] = {a4.x, a4.y, a4.z, a4.w};
#pragma unroll
            for (int i = 0; i < 4; i++) {
                acc[i][0] = fmaf(aa[i], v0.x, acc[i][0]);
                acc[i][1] = fmaf(aa[i], v0.y, acc[i][1]);
                acc[i][2] = fmaf(aa[i], v0.z, acc[i][2]);
                acc[i][3] = fmaf(aa[i], v0.w, acc[i][3]);
                acc[i][4] = fmaf(aa[i], v1.x, acc[i][4]);
                acc[i][5] = fmaf(aa[i], v1.y, acc[i][5]);
                acc[i][6] = fmaf(aa[i], v1.z, acc[i][6]);
                acc[i][7] = fmaf(aa[i], v1.w, acc[i][7]);
            }
        }
        __syncthreads();
    }

    float* op = O + ((size_t)b*T_ + qBase) * QCOLS_ + (size_t)h*HD_;
#pragma unroll
    for (int i = 0; i < 4; i++) {
        float inv = 1.0f / l[i];
        float4 o0 = make_float4(acc[i][0]*inv, acc[i][1]*inv, acc[i][2]*inv, acc[i][3]*inv);
        float4 o1 = make_float4(acc[i][4]*inv, acc[i][5]*inv, acc[i][6]*inv, acc[i][7]*inv);
        *(float4*)(op + (size_t)(4*ty + i)*QCOLS_ + 8*tx)     = o0;
        *(float4*)(op + (size_t)(4*ty + i)*QCOLS_ + 8*tx + 4) = o1;
    }
}

// ============================================================================
// launch
// ============================================================================
extern "C" void kernel_launch(void* const* d_in, const int* in_sizes, int n_in,
                              void* d_out, int out_size)
{
    const float* x  = (const float*)d_in[0];
    const float* wq = (const float*)d_in[1];
    const float* wk = (const float*)d_in[2];
    const float* wv = (const float*)d_in[3];
    const float* wo = (const float*)d_in[4];
    const float* qg = (const float*)d_in[5];
    const float* kg = (const float*)d_in[6];
    float* out = (float*)d_out;

    float *q, *k, *v, *o;
    cudaGetSymbolAddress((void**)&q, g_q);
    cudaGetSymbolAddress((void**)&k, g_k);
    cudaGetSymbolAddress((void**)&v, g_v);
    cudaGetSymbolAddress((void**)&o, g_o);

    static bool attr_set = false;
    if (!attr_set) {
        cudaFuncSetAttribute(gemm_tf32, cudaFuncAttributeMaxDynamicSharedMemorySize, GEMM_SMEM);
        cudaFuncSetAttribute(attn_k, cudaFuncAttributeMaxDynamicSharedMemorySize, ATTN_SMEM);
        attr_set = true;
    }

    // projections (tf32 tensor cores)
    gemm_tf32<<<dim3(QCOLS_/128, BT_/128), 256, GEMM_SMEM>>>(x, wq, q, BT_, QCOLS_, D_);
    gemm_tf32<<<dim3(KCOLS_/128, BT_/128), 256, GEMM_SMEM>>>(x, wk, k, BT_, KCOLS_, D_);
    gemm_tf32<<<dim3(KCOLS_/128, BT_/128), 256, GEMM_SMEM>>>(x, wv, v, BT_, KCOLS_, D_);

    // QK-norm (fold attention scale into q)
    rmsnorm_k<<<(BT_*H_)/8, 256>>>(q, qg, BT_*H_, SCALE_);
    rmsnorm_k<<<(BT_*KVH_)/8, 256>>>(k, kg, BT_*KVH_, 1.0f);

    // attention (fp32 SIMT, unchanged this round)
    attn_k<<<dim3(T_/64, B_*H_), 256, ATTN_SMEM>>>(q, k, v, o);

    // output projection
    gemm_tf32<<<dim3(D_/128, BT_/128), 256, GEMM_SMEM>>>(o, wo, out, BT_, D_, D_);
}

// round 5
// speedup vs baseline: 3.1912x; 1.6852x over previous
#include <cuda_runtime.h>
#include <math.h>

// ---- problem constants ----
#define D_   2048
#define H_   16
#define KVH_ 4
#define HD_  128
#define B_   2
#define T_   2048
#define BT_  (B_*T_)          // 4096
#define QCOLS_ (H_*HD_)       // 2048
#define KCOLS_ (KVH_*HD_)     // 512
#define CAP_ 50.0f
#define SCALE_ 0.08838834764831845f  // 128^-0.5

// ---- scratch (static device arrays; no allocations allowed) ----
static __device__ float g_q[BT_*QCOLS_];
static __device__ float g_k[BT_*KCOLS_];
static __device__ float g_v[BT_*KCOLS_];
static __device__ float g_o[BT_*QCOLS_];

// ============================================================================
// tf32 mma helpers
// ============================================================================
__device__ __forceinline__ unsigned f2tf32(float x) {
    unsigned u;
    asm("cvt.rna.tf32.f32 %0, %1;" : "=r"(u) : "f"(x));
    return u;
}

__device__ __forceinline__ void mma_tf32(float* c, const unsigned* a, const unsigned* b) {
    asm volatile(
        "mma.sync.aligned.m16n8k8.row.col.f32.tf32.tf32.f32 "
        "{%0,%1,%2,%3}, {%4,%5,%6,%7}, {%8,%9}, {%0,%1,%2,%3};"
        : "+f"(c[0]), "+f"(c[1]), "+f"(c[2]), "+f"(c[3])
        : "r"(a[0]), "r"(a[1]), "r"(a[2]), "r"(a[3]), "r"(b[0]), "r"(b[1]));
}

__device__ __forceinline__ float tanh_fast(float x) {
    float r;
    asm("tanh.approx.f32 %0, %1;" : "=f"(r) : "f"(x));
    return r;
}

__device__ __forceinline__ void cp_async16(void* smem_dst, const void* gsrc) {
    unsigned saddr = (unsigned)__cvta_generic_to_shared(smem_dst);
    asm volatile("cp.async.cg.shared.global [%0], [%1], 16;" :: "r"(saddr), "l"(gsrc));
}
#define CP_COMMIT() asm volatile("cp.async.commit_group;")
#define CP_WAIT0()  asm volatile("cp.async.wait_group 0;")

// ============================================================================
// tf32 tensor-core GEMM: C[M,N] = A[M,K] * B[N,K]^T  (row-major, M,N %128==0,
// K %32==0). 128x128x32 CTA tile, 8 warps (4x2), warp tile 32x64,
// 2-stage cp.async pipeline. smem rows padded to 36 floats (conflict-free).
// ============================================================================
#define BK_ 32
#define LDP_ 36
#define GEMM_SMEM (4 * 128 * LDP_ * (int)sizeof(float))  // 2 stages x (A+B)

__global__ __launch_bounds__(256) void gemm_tf32(
    const float* __restrict__ A, const float* __restrict__ Bw,
    float* __restrict__ C, int M, int N, int K)
{
    extern __shared__ float sm[];
    float* AsBase = sm;                    // [2][128*LDP_]
    float* BsBase = sm + 2 * 128 * LDP_;   // [2][128*LDP_]

    const int tid  = threadIdx.x;
    const int lane = tid & 31;
    const int warp = tid >> 5;
    const int wm = (warp & 3) * 32;    // warp row offset within tile
    const int wn = (warp >> 2) * 64;   // warp col offset within tile
    const int rowBase = blockIdx.y * 128;
    const int colBase = blockIdx.x * 128;

    const int lr = tid >> 3;          // load row sub-index (0..31)
    const int lc = (tid & 7) * 4;     // load col (float index, 16B steps)

    float acc[2][8][4];
#pragma unroll
    for (int mi = 0; mi < 2; mi++)
#pragma unroll
        for (int ni = 0; ni < 8; ni++)
#pragma unroll
            for (int q = 0; q < 4; q++) acc[mi][ni][q] = 0.f;

    const int ntiles = K / BK_;

    {
        float* as = AsBase;
        float* bs = BsBase;
#pragma unroll
        for (int it = 0; it < 4; it++) {
            int r = it * 32 + lr;
            cp_async16(as + r * LDP_ + lc, A  + (size_t)(rowBase + r) * K + lc);
            cp_async16(bs + r * LDP_ + lc, Bw + (size_t)(colBase + r) * K + lc);
        }
        CP_COMMIT();
    }

    int cur = 0;
    for (int t = 0; t < ntiles; t++) {
        CP_WAIT0();
        __syncthreads();

        if (t + 1 < ntiles) {
            int k0 = (t + 1) * BK_;
            float* as = AsBase + (cur ^ 1) * 128 * LDP_;
            float* bs = BsBase + (cur ^ 1) * 128 * LDP_;
#pragma unroll
            for (int it = 0; it < 4; it++) {
                int r = it * 32 + lr;
                cp_async16(as + r * LDP_ + lc, A  + (size_t)(rowBase + r) * K + k0 + lc);
                cp_async16(bs + r * LDP_ + lc, Bw + (size_t)(colBase + r) * K + k0 + lc);
            }
            CP_COMMIT();
        }

        const float* as = AsBase + cur * 128 * LDP_;
        const float* bs = BsBase + cur * 128 * LDP_;
#pragma unroll
        for (int kk = 0; kk < 4; kk++) {
            const int k = kk * 8 + (lane & 3);
            unsigned af[2][4], bf[8][2];
#pragma unroll
            for (int mi = 0; mi < 2; mi++) {
                int r = wm + mi * 16 + (lane >> 2);
                af[mi][0] = f2tf32(as[r       * LDP_ + k]);
                af[mi][1] = f2tf32(as[(r + 8) * LDP_ + k]);
                af[mi][2] = f2tf32(as[r       * LDP_ + k + 4]);
                af[mi][3] = f2tf32(as[(r + 8) * LDP_ + k + 4]);
            }
#pragma unroll
            for (int ni = 0; ni < 8; ni++) {
                int n = wn + ni * 8 + (lane >> 2);
                bf[ni][0] = f2tf32(bs[n * LDP_ + k]);
                bf[ni][1] = f2tf32(bs[n * LDP_ + k + 4]);
            }
#pragma unroll
            for (int mi = 0; mi < 2; mi++)
#pragma unroll
                for (int ni = 0; ni < 8; ni++)
                    mma_tf32(acc[mi][ni], af[mi], bf[ni]);
        }
        cur ^= 1;
    }

#pragma unroll
    for (int mi = 0; mi < 2; mi++) {
        int r0 = rowBase + wm + mi * 16 + (lane >> 2);
#pragma unroll
        for (int ni = 0; ni < 8; ni++) {
            int c0 = colBase + wn + ni * 8 + (lane & 3) * 2;
            *(float2*)&C[(size_t)r0       * N + c0] = make_float2(acc[mi][ni][0], acc[mi][ni][1]);
            *(float2*)&C[(size_t)(r0 + 8) * N + c0] = make_float2(acc[mi][ni][2], acc[mi][ni][3]);
        }
    }
}

// ============================================================================
// RMSNorm: one warp per 128-element row, in place. Scale folded in (q gets HD^-0.5).
// ============================================================================
__global__ __launch_bounds__(256) void rmsnorm_k(
    float* __restrict__ data, const float* __restrict__ gamma,
    int nrows, float scale)
{
    int row  = blockIdx.x * 8 + (threadIdx.x >> 5);
    int lane = threadIdx.x & 31;
    if (row >= nrows) return;
    float4 v = ((float4*)data)[(size_t)row * 32 + lane];
    float ss = v.x*v.x + v.y*v.y + v.z*v.z + v.w*v.w;
#pragma unroll
    for (int off = 16; off > 0; off >>= 1)
        ss += __shfl_xor_sync(0xffffffffu, ss, off);
    float r = rsqrtf(ss * (1.0f/128.0f) + 1e-6f) * scale;
    float4 g = ((const float4*)gamma)[lane];
    v.x *= r * g.x; v.y *= r * g.y; v.z *= r * g.z; v.w *= r * g.w;
    ((float4*)data)[(size_t)row * 32 + lane] = v;
}

// ============================================================================
// Tensor-core flash attention (causal, tanh softcap).
// CTA: 128 threads (4 warps). Tile: 64 q-rows x 64 k-cols, HD=128.
// Warp w owns q rows [16w, 16w+16). S and P live in mma C-fragments; P feeds
// PV as A-fragments via the kappa-permutation (a={c0,c2,c1,c3}, V k-permuted).
// smem (all pre-converted tf32):
//   Qs[64][132], Ks[64][132]  (pad-132: frag LDS bank = 4r+k, conflict-free)
//   Vt[32][64][4] stride 260  (d-grouped transpose: STS.128 + LDS conflict-free)
// ============================================================================
#define AT_LDK 132
#define AT_VROW 260            // words per d4-group row: 64 keys * 4 + pad 4
#define ATTN_SMEM ((2*64*AT_LDK + 32*AT_VROW) * (int)sizeof(unsigned))

__global__ __launch_bounds__(128) void attn_mma(
    const float* __restrict__ Q, const float* __restrict__ Kk,
    const float* __restrict__ Vv, float* __restrict__ O)
{
    extern __shared__ unsigned smu[];
    unsigned* Qs = smu;
    unsigned* Ks = Qs + 64 * AT_LDK;
    unsigned* Vt = Ks + 64 * AT_LDK;

    const int tid  = threadIdx.x;
    const int lane = tid & 31;
    const int warp = tid >> 5;
    const int gid  = lane >> 2;      // group id (row within frag)
    const int m4   = lane & 3;       // thread-in-group

    const int bh = blockIdx.y;
    const int b = bh >> 4, h = bh & 15, kvh = h >> 2;
    const int qt = gridDim.x - 1 - blockIdx.x;     // heavy tiles first
    const int qBase = qt * 64;

    const float* qp = Q  + (size_t)b*T_*QCOLS_ + (size_t)h*HD_;
    const float* kp = Kk + (size_t)b*T_*KCOLS_ + (size_t)kvh*HD_;
    const float* vp = Vv + (size_t)b*T_*KCOLS_ + (size_t)kvh*HD_;

    // ---- load Q tile (64x128) -> Qs as tf32 ----
#pragma unroll
    for (int it = 0; it < 16; it++) {
        int i = it * 128 + tid;
        int r = i >> 5;
        int c4 = (i & 31) << 2;
        float4 v = *(const float4*)(qp + (size_t)(qBase + r) * QCOLS_ + c4);
        unsigned* dst = Qs + r * AT_LDK + c4;
        dst[0] = f2tf32(v.x); dst[1] = f2tf32(v.y);
        dst[2] = f2tf32(v.z); dst[3] = f2tf32(v.w);
    }

    // softmax state for the warp's two frag rows
    float m0 = -INFINITY, m1 = -INFINITY, l0 = 0.f, l1 = 0.f;
    float o[16][4];
#pragma unroll
    for (int nf = 0; nf < 16; nf++)
#pragma unroll
        for (int q = 0; q < 4; q++) o[nf][q] = 0.f;

    const int r0g = qBase + 16 * warp + gid;   // global q row (frag row 0)
    const int r1g = r0g + 8;

    for (int jt = 0; jt <= qt; jt++) {
        const int kBase = jt * 64;

        // ---- load K (64x128) -> Ks tf32; V (64x128) -> Vt tf32 transposed ----
#pragma unroll
        for (int it = 0; it < 16; it++) {
            int i = it * 128 + tid;
            int r = i >> 5;          // key row (const per warp)
            int c4 = (i & 31) << 2;  // d offset = 4*lane
            const float4 kv = *(const float4*)(kp + (size_t)(kBase + r) * KCOLS_ + c4);
            unsigned* kd = Ks + r * AT_LDK + c4;
            kd[0] = f2tf32(kv.x); kd[1] = f2tf32(kv.y);
            kd[2] = f2tf32(kv.z); kd[3] = f2tf32(kv.w);
            const float4 vv = *(const float4*)(vp + (size_t)(kBase + r) * KCOLS_ + c4);
            uint4 vt;
            vt.x = f2tf32(vv.x); vt.y = f2tf32(vv.y);
            vt.z = f2tf32(vv.z); vt.w = f2tf32(vv.w);
            // Vt[d>>2][key][d&3]: contiguous 4 words per thread -> STS.128
            *(uint4*)(Vt + (c4 >> 2) * AT_VROW + r * 4) = vt;
        }
        __syncthreads();

        // ---- S = Q . K^T (tf32 mma) ----
        float s[8][4];
#pragma unroll
        for (int nf = 0; nf < 8; nf++)
#pragma unroll
            for (int q = 0; q < 4; q++) s[nf][q] = 0.f;

#pragma unroll
        for (int kc = 0; kc < 16; kc++) {
            const int k = kc * 8 + m4;
            const int r = 16 * warp + gid;
            unsigned a[4];
            a[0] = Qs[r       * AT_LDK + k];
            a[1] = Qs[(r + 8) * AT_LDK + k];
            a[2] = Qs[r       * AT_LDK + k + 4];
            a[3] = Qs[(r + 8) * AT_LDK + k + 4];
#pragma unroll
            for (int nf = 0; nf < 8; nf++) {
                const int n = nf * 8 + gid;
                unsigned bq[2];
                bq[0] = Ks[n * AT_LDK + k];
                bq[1] = Ks[n * AT_LDK + k + 4];
                mma_tf32(s[nf], a, bq);
            }
        }

        // ---- softcap + causal mask ----
        const int cb = kBase + 2 * m4;
#pragma unroll
        for (int nf = 0; nf < 8; nf++) {
#pragma unroll
            for (int q = 0; q < 4; q++) {
                int col = cb + 8 * nf + (q & 1);
                int row = (q < 2) ? r0g : r1g;
                float val = CAP_ * tanh_fast(s[nf][q] * (1.0f / CAP_));
                s[nf][q] = (col > row) ? -INFINITY : val;
            }
        }

        // ---- online softmax (row group = 4 lanes, shfl 1,2) ----
        float rmax0 = -INFINITY, rmax1 = -INFINITY;
#pragma unroll
        for (int nf = 0; nf < 8; nf++) {
            rmax0 = fmaxf(rmax0, fmaxf(s[nf][0], s[nf][1]));
            rmax1 = fmaxf(rmax1, fmaxf(s[nf][2], s[nf][3]));
        }
#pragma unroll
        for (int off = 1; off <= 2; off <<= 1) {
            rmax0 = fmaxf(rmax0, __shfl_xor_sync(0xffffffffu, rmax0, off));
            rmax1 = fmaxf(rmax1, __shfl_xor_sync(0xffffffffu, rmax1, off));
        }
        float mn0 = fmaxf(m0, rmax0), mn1 = fmaxf(m1, rmax1);
        float al0 = __expf(m0 - mn0), al1 = __expf(m1 - mn1);
        m0 = mn0; m1 = mn1;

        float rs0 = 0.f, rs1 = 0.f;
#pragma unroll
        for (int nf = 0; nf < 8; nf++) {
            float p0 = __expf(s[nf][0] - mn0);
            float p1 = __expf(s[nf][1] - mn0);
            float p2 = __expf(s[nf][2] - mn1);
            float p3 = __expf(s[nf][3] - mn1);
            rs0 += p0 + p1; rs1 += p2 + p3;
            s[nf][0] = p0; s[nf][1] = p1; s[nf][2] = p2; s[nf][3] = p3;
        }
#pragma unroll
        for (int off = 1; off <= 2; off <<= 1) {
            rs0 += __shfl_xor_sync(0xffffffffu, rs0, off);
            rs1 += __shfl_xor_sync(0xffffffffu, rs1, off);
        }
        l0 = l0 * al0 + rs0;
        l1 = l1 * al1 + rs1;
#pragma unroll
        for (int nf = 0; nf < 16; nf++) {
            o[nf][0] *= al0; o[nf][1] *= al0;
            o[nf][2] *= al1; o[nf][3] *= al1;
        }

        // ---- O += P . V (tf32 mma, kappa-permuted V) ----
        const int vlow = (lane >> 4) * AT_VROW + ((lane >> 2) & 3) + 8 * m4;
#pragma unroll
        for (int kc = 0; kc < 8; kc++) {
            unsigned pa[4];
            pa[0] = f2tf32(s[kc][0]);   // c0 -> a0
            pa[1] = f2tf32(s[kc][2]);   // c2 -> a1
            pa[2] = f2tf32(s[kc][1]);   // c1 -> a2
            pa[3] = f2tf32(s[kc][3]);   // c3 -> a3
#pragma unroll
            for (int nf = 0; nf < 16; nf++) {
                const unsigned* vb = Vt + 2 * nf * AT_VROW + 32 * kc + vlow;
                unsigned bv[2];
                bv[0] = vb[0];   // key 8kc + 2m
                bv[1] = vb[4];   // key 8kc + 2m + 1
                mma_tf32(o[nf], pa, bv);
            }
        }
        __syncthreads();
    }

    // ---- epilogue: /l, store ----
    float inv0 = 1.0f / l0, inv1 = 1.0f / l1;
    float* op0 = O + ((size_t)b*T_ + r0g) * QCOLS_ + (size_t)h*HD_;
    float* op1 = O + ((size_t)b*T_ + r1g) * QCOLS_ + (size_t)h*HD_;
#pragma unroll
    for (int nf = 0; nf < 16; nf++) {
        int col = 8 * nf + 2 * m4;
        *(float2*)(op0 + col) = make_float2(o[nf][0] * inv0, o[nf][1] * inv0);
        *(float2*)(op1 + col) = make_float2(o[nf][2] * inv1, o[nf][3] * inv1);
    }
}

// ============================================================================
// launch
// ============================================================================
extern "C" void kernel_launch(void* const* d_in, const int* in_sizes, int n_in,
                              void* d_out, int out_size)
{
    const float* x  = (const float*)d_in[0];
    const float* wq = (const float*)d_in[1];
    const float* wk = (const float*)d_in[2];
    const float* wv = (const float*)d_in[3];
    const float* wo = (const float*)d_in[4];
    const float* qg = (const float*)d_in[5];
    const float* kg = (const float*)d_in[6];
    float* out = (float*)d_out;

    float *q, *k, *v, *o;
    cudaGetSymbolAddress((void**)&q, g_q);
    cudaGetSymbolAddress((void**)&k, g_k);
    cudaGetSymbolAddress((void**)&v, g_v);
    cudaGetSymbolAddress((void**)&o, g_o);

    static bool attr_set = false;
    if (!attr_set) {
        cudaFuncSetAttribute(gemm_tf32, cudaFuncAttributeMaxDynamicSharedMemorySize, GEMM_SMEM);
        cudaFuncSetAttribute(attn_mma, cudaFuncAttributeMaxDynamicSharedMemorySize, ATTN_SMEM);
        attr_set = true;
    }

    // projections (tf32 tensor cores)
    gemm_tf32<<<dim3(QCOLS_/128, BT_/128), 256, GEMM_SMEM>>>(x, wq, q, BT_, QCOLS_, D_);
    gemm_tf32<<<dim3(KCOLS_/128, BT_/128), 256, GEMM_SMEM>>>(x, wk, k, BT_, KCOLS_, D_);
    gemm_tf32<<<dim3(KCOLS_/128, BT_/128), 256, GEMM_SMEM>>>(x, wv, v, BT_, KCOLS_, D_);

    // QK-norm (fold attention scale into q)
    rmsnorm_k<<<(BT_*H_)/8, 256>>>(q, qg, BT_*H_, SCALE_);
    rmsnorm_k<<<(BT_*KVH_)/8, 256>>>(k, kg, BT_*KVH_, 1.0f);

    // attention (tf32 tensor cores)
    attn_mma<<<dim3(T_/64, B_*H_), 128, ATTN_SMEM>>>(q, k, v, o);

    // output projection
    gemm_tf32<<<dim3(D_/128, BT_/128), 256, GEMM_SMEM>>>(o, wo, out, BT_, D_, D_);
}